// round 1
// baseline (speedup 1.0000x reference)
#include <cuda_runtime.h>

typedef unsigned long long u64;

#define B_ 2048
#define I_ 512
#define O_ 256
#define BM 16
#define NTHREADS 512
// dynamic smem: zs[512] + namd[512][32]
#define SMEM_BYTES ((I_ + I_ * 2 * BM) * (int)sizeof(float))

__device__ __forceinline__ u64 fma2_(u64 a, u64 b, u64 c) {
    u64 d;
    asm("fma.rn.f32x2 %0, %1, %2, %3;" : "=l"(d) : "l"(a), "l"(b), "l"(c));
    return d;
}
__device__ __forceinline__ u64 mul2_(u64 a, u64 b) {
    u64 d;
    asm("mul.rn.f32x2 %0, %1, %2;" : "=l"(d) : "l"(a), "l"(b));
    return d;
}

__global__ __launch_bounds__(NTHREADS, 1) void l0conj_kernel(
    const float* __restrict__ x,      // [B_, I_]
    const float* __restrict__ w,      // [I_, O_]
    const float* __restrict__ qz,     // [I_]
    float* __restrict__ out)          // [B_, O_]
{
    extern __shared__ float smem[];
    float* zs = smem;                  // [I_]
    float* namd = smem + I_;           // [I_][2*BM], namd[i*32+2b] = namd[i*32+2b+1] = x[b0+b][i]*z[i]-1

    const int tid = threadIdx.x;
    const int b0 = blockIdx.x * BM;

    // z[i] = clip(sigmoid(qz[i]) * 1.2 - 0.1, 0, 1)
    if (tid < I_) {
        float q = qz[tid];
        float pi = 1.0f / (1.0f + expf(-q));
        float z = fmaf(pi, 1.2f, -0.1f);
        zs[tid] = fminf(fmaxf(z, 0.0f), 1.0f);
    }
    __syncthreads();

    // Stage nam = x*z - 1, duplicated per value for free f32x2 dup-pairs.
    // k -> (b = k&15, i = k>>4): smem writes are conflict-free (32 consecutive floats/warp);
    // global reads are scattered-but-L1-resident (32KB tile).
    for (int k = tid; k < BM * I_; k += NTHREADS) {
        int b = k & (BM - 1);
        int i = k >> 4;
        float v = fmaf(x[(b0 + b) * I_ + i], zs[i], -1.0f);
        int base = i * (2 * BM) + 2 * b;
        namd[base] = v;
        namd[base + 1] = v;
    }
    __syncthreads();

    // Thread -> 2 consecutive o's (one w-pair per i) x 4 consecutive b's (4 accumulators)
    const int o2 = (tid & 127) * 2;        // o, o+1
    const int b4 = (tid >> 7) * 4;         // b4..b4+3 within the 16-row tile
    const u64* wq = (const u64*)(w + o2);  // wq[i * (O_/2)] = (w[i][o2], w[i][o2+1])
    const float* arow = namd + 2 * b4;

    const u64 one2 = 0x3F8000003F800000ULL;  // (1.0f, 1.0f)
    u64 p0 = one2, p1 = one2, p2 = one2, p3 = one2;

    // Double-buffered w prefetch (one 4-i group ahead) to cover L2-hit latency.
    u64 wc[4], wn[4];
#pragma unroll
    for (int u = 0; u < 4; ++u) wc[u] = wq[u * (O_ / 2)];

#pragma unroll 1
    for (int it = 0; it < I_ / 4; ++it) {
        const int inx = ((it + 1) & (I_ / 4 - 1)) * 4;  // wraps to 0 on last iter (harmless reload)
#pragma unroll
        for (int u = 0; u < 4; ++u) wn[u] = wq[(inx + u) * (O_ / 2)];

        const int ib = it * 4;
#pragma unroll
        for (int u = 0; u < 4; ++u) {
            const ulonglong2* ap =
                (const ulonglong2*)(arow + (ib + u) * (2 * BM));
            ulonglong2 al = ap[0];   // al.x = (nam[b4],   nam[b4]);   al.y = (nam[b4+1], dup)
            ulonglong2 ah = ap[1];   // ah.x = (nam[b4+2], dup);       ah.y = (nam[b4+3], dup)
            u64 wv = wc[u];          // (w[i][o2], w[i][o2+1])
            p0 = mul2_(p0, fma2_(al.x, wv, one2));
            p1 = mul2_(p1, fma2_(al.y, wv, one2));
            p2 = mul2_(p2, fma2_(ah.x, wv, one2));
            p3 = mul2_(p3, fma2_(ah.y, wv, one2));
        }
#pragma unroll
        for (int u = 0; u < 4; ++u) wc[u] = wn[u];
    }

    // Epilogue: each accumulator is (out[row][o2], out[row][o2+1])
    float* orow = out + (b0 + b4) * O_ + o2;
    *(u64*)(orow + 0 * O_) = p0;
    *(u64*)(orow + 1 * O_) = p1;
    *(u64*)(orow + 2 * O_) = p2;
    *(u64*)(orow + 3 * O_) = p3;
}

extern "C" void kernel_launch(void* const* d_in, const int* in_sizes, int n_in,
                              void* d_out, int out_size) {
    const float* x = nullptr;
    const float* w = nullptr;
    const float* qz = nullptr;
    for (int i = 0; i < n_in; ++i) {
        if (in_sizes[i] == B_ * I_)      x  = (const float*)d_in[i];
        else if (in_sizes[i] == I_ * O_) w  = (const float*)d_in[i];
        else if (in_sizes[i] == I_)      qz = (const float*)d_in[i];
    }
    cudaFuncSetAttribute(l0conj_kernel,
                         cudaFuncAttributeMaxDynamicSharedMemorySize, SMEM_BYTES);
    l0conj_kernel<<<B_ / BM, NTHREADS, SMEM_BYTES>>>(x, w, qz, (float*)d_out);
}